// round 2
// baseline (speedup 1.0000x reference)
#include <cuda_runtime.h>
#include <math.h>
#include <stdint.h>

#define FULLMASK 0xffffffffu

static __device__ __forceinline__ float finf() { return __int_as_float(0x7f800000); }

// One batch per 8-lane group; 4 batches per warp; 128 threads/block -> 16 batches/block.
__global__ void __launch_bounds__(128) bwm_kernel(
    const float* __restrict__ mem,     // [B,8,64]
    const float* __restrict__ act_in,  // [B,8]
    const float* __restrict__ gates,   // [B,8]
    const float* __restrict__ thr,     // [B,8]
    const float* __restrict__ rstr,    // [B,8]
    const float* __restrict__ W,       // [B,8,8]
    const float* __restrict__ maint,   // [B,8]
    const float* __restrict__ inp,     // [B,64]
    const float* __restrict__ gsig,    // [B,8]
    const float* __restrict__ rsig,    // [B,8]
    const int*   __restrict__ dtp,     // scalar
    float* __restrict__ out, int B)
{
    const int gtid = blockIdx.x * blockDim.x + threadIdx.x;
    const int warp = gtid >> 5;
    const int lane = threadIdx.x & 31;
    const int grp  = lane >> 3;     // which batch within the warp (0..3)
    const int sub  = lane & 7;      // lane within batch group == slot index for scalars
    const int b0   = warp * 4 + grp;
    const bool valid = (b0 < B);
    const int b = valid ? b0 : (B - 1);

    // dt: handle int32 or float32 storage (dt=1 -> bits 0x1 -> int path)
    int dti = *dtp;
    float dt = (dti >= -1000000 && dti <= 1000000) ? (float)dti : __int_as_float(dti);

    // ---- loads -------------------------------------------------------------
    float m[8][8];
    {
        const float* mrow = mem + (size_t)b * 512 + sub * 8;
        #pragma unroll
        for (int s = 0; s < 8; s++) {
            float4 v0 = *(const float4*)(mrow + s * 64);
            float4 v1 = *(const float4*)(mrow + s * 64 + 4);
            m[s][0] = v0.x; m[s][1] = v0.y; m[s][2] = v0.z; m[s][3] = v0.w;
            m[s][4] = v1.x; m[s][5] = v1.y; m[s][6] = v1.z; m[s][7] = v1.w;
        }
    }
    float wr[8];
    {
        const float* wp = W + (size_t)b * 64 + sub * 8;   // lane holds interference row `sub`
        float4 v0 = *(const float4*)wp;
        float4 v1 = *(const float4*)(wp + 4);
        wr[0] = v0.x; wr[1] = v0.y; wr[2] = v0.z; wr[3] = v0.w;
        wr[4] = v1.x; wr[5] = v1.y; wr[6] = v1.z; wr[7] = v1.w;
    }
    const int sbase = b * 8 + sub;
    float a0  = act_in[sbase];
    float gat = gates[sbase];
    float th  = thr[sbase];
    float rst = rstr[sbase];
    float mnt = maint[sbase];
    float gsg = gsig[sbase];
    float rsg = rsig[sbase];

    // ---- target slot (argmin semantics, stable first-index tie-break) ------
    bool avail = a0 < 0.2f;
    unsigned avb = (__ballot_sync(FULLMASK, avail) >> (grp * 8)) & 0xffu;
    float key = avb ? (avail ? a0 : finf()) : a0;
    int idx = sub;
    #pragma unroll
    for (int off = 4; off >= 1; off >>= 1) {
        float ok = __shfl_xor_sync(FULLMASK, key, off);
        int   oi = __shfl_xor_sync(FULLMASK, idx, off);
        bool take = (ok < key) || (ok == key && oi < idx);
        key = take ? ok : key;
        idx = take ? oi : idx;
    }
    const int ts = idx;  // all lanes in the group agree

    // ---- decay -------------------------------------------------------------
    float a = a0 * 0.9f;
    #pragma unroll
    for (int s = 0; s < 8; s++)
        #pragma unroll
        for (int k = 0; k < 8; k++) m[s][k] *= 0.95f;
    const unsigned actm = (__ballot_sync(FULLMASK, a > 0.1f) >> (grp * 8)) & 0xffu;

    // ---- initial squared norms (maintained incrementally afterwards) -------
    float ni[8];
    #pragma unroll
    for (int s = 0; s < 8; s++) {
        float pa = m[s][0] * m[s][0];
        float pb = m[s][1] * m[s][1];
        pa = fmaf(m[s][2], m[s][2], pa); pb = fmaf(m[s][3], m[s][3], pb);
        pa = fmaf(m[s][4], m[s][4], pa); pb = fmaf(m[s][5], m[s][5], pb);
        pa = fmaf(m[s][6], m[s][6], pa); pb = fmaf(m[s][7], m[s][7], pb);
        float p = pa + pb;
        p += __shfl_xor_sync(FULLMASK, p, 4);
        p += __shfl_xor_sync(FULLMASK, p, 2);
        p += __shfl_xor_sync(FULLMASK, p, 1);
        ni[s] = p;
    }

    // ---- interference: 56 serial (i,j) updates -----------------------------
    #pragma unroll
    for (int i = 0; i < 8; i++) {
        #pragma unroll
        for (int j = 0; j < 8; j++) {
            if (i == j) continue;
            float pa = m[i][0] * m[j][0];
            float pb = m[i][1] * m[j][1];
            pa = fmaf(m[i][2], m[j][2], pa); pb = fmaf(m[i][3], m[j][3], pb);
            pa = fmaf(m[i][4], m[j][4], pa); pb = fmaf(m[i][5], m[j][5], pb);
            pa = fmaf(m[i][6], m[j][6], pa); pb = fmaf(m[i][7], m[j][7], pb);
            float p = pa + pb;
            p += __shfl_xor_sync(FULLMASK, p, 4);
            p += __shfl_xor_sync(FULLMASK, p, 2);
            p += __shfl_xor_sync(FULLMASK, p, 1);
            float w = __shfl_sync(FULLMASK, wr[j], i, 8);   // W[i][j]
            float sim = p * rsqrtf(fmaxf(ni[i] * ni[j], 1e-24f));
            bool cond = ((actm >> i) & 1u) && ((actm >> j) & 1u);
            float c = cond ? (w * sim * 0.1f) : 0.0f;
            #pragma unroll
            for (int k = 0; k < 8; k++) m[i][k] = fmaf(-c, m[j][k], m[i][k]);
            // ||mi - c*mj||^2 = ni - 2 c p + c^2 nj
            ni[i] = fmaf(c, fmaf(c, ni[j], -2.0f * p), ni[i]);
        }
    }

    // ---- inputs (loaded late to relieve register pressure) -----------------
    float xin[8];
    {
        const float* ip = inp + (size_t)b * 64 + sub * 8;
        float4 v0 = *(const float4*)ip;
        float4 v1 = *(const float4*)(ip + 4);
        xin[0] = v0.x; xin[1] = v0.y; xin[2] = v0.z; xin[3] = v0.w;
        xin[4] = v1.x; xin[5] = v1.y; xin[6] = v1.z; xin[7] = v1.w;
    }

    // ---- gating ------------------------------------------------------------
    float g = fmaf(0.3f, fminf(fmaxf(gsg, 0.0f), 1.0f), 0.7f * gat);
    float gs   = __shfl_sync(FULLMASK, g,  ts, 8);
    float thts = __shfl_sync(FULLMASK, th, ts, 8);
    bool  write = gs > thts;

    // ||inputs||
    float innorm;
    {
        float pa = xin[0] * xin[0];
        float pb = xin[1] * xin[1];
        pa = fmaf(xin[2], xin[2], pa); pb = fmaf(xin[3], xin[3], pb);
        pa = fmaf(xin[4], xin[4], pa); pb = fmaf(xin[5], xin[5], pb);
        pa = fmaf(xin[6], xin[6], pa); pb = fmaf(xin[7], xin[7], pb);
        float p = pa + pb;
        p += __shfl_xor_sync(FULLMASK, p, 4);
        p += __shfl_xor_sync(FULLMASK, p, 2);
        p += __shfl_xor_sync(FULLMASK, p, 1);
        innorm = sqrtf(p);
    }

    // ---- refresh -----------------------------------------------------------
    float ru = fminf(fmaxf(rsg, 0.0f), 1.0f);
    float rs = (ru > 0.1f) ? rst * ru : 0.0f;
    if (write && sub == ts) a = innorm;
    a += rs;

    // ---- maintenance currents ---------------------------------------------
    float mc = (a > 0.1f) ? fmaf(fmaf(0.5f, a, -mnt), 0.1f * dt, mnt) : mnt * 0.95f;

    // ---- capacity deactivation (stable double-argsort rank) ----------------
    bool active = a > 0.1f;
    unsigned ab = (__ballot_sync(FULLMASK, active) >> (grp * 8)) & 0xffu;
    int ndeact = __popc(ab) - 4;   // WM_CAPACITY=4; may be <= 0
    float key2 = active ? a : finf();
    int rank = 0;
    #pragma unroll
    for (int k2 = 0; k2 < 8; k2++) {
        float vk = __shfl_sync(FULLMASK, key2, k2, 8);
        rank += ((vk < key2) || (vk == key2 && k2 < sub)) ? 1 : 0;
    }
    bool deact = active && (rank < ndeact);
    if (deact) a *= 0.5f;
    unsigned db = (__ballot_sync(FULLMASK, deact) >> (grp * 8)) & 0xffu;

    // ---- fused epilogue on m: blend(ts) then *(1+rs_s) then *0.7 if deact --
    float bco = gs * 0.3f;
    #pragma unroll
    for (int s = 0; s < 8; s++) {
        float rss = __shfl_sync(FULLMASK, rs, s, 8);
        float sc = (1.0f + rss) * (((db >> s) & 1u) ? 0.7f : 1.0f);
        float f  = (write && s == ts) ? bco : 0.0f;
        float A  = (1.0f - f) * sc;
        float Bc = f * sc;
        #pragma unroll
        for (int k = 0; k < 8; k++)
            m[s][k] = fmaf(A, m[s][k], Bc * xin[k]);
    }

    // ---- batch-level reductions -------------------------------------------
    float ta = a;
    ta += __shfl_xor_sync(FULLMASK, ta, 4);
    ta += __shfl_xor_sync(FULLMASK, ta, 2);
    ta += __shfl_xor_sync(FULLMASK, ta, 1);
    float msum = mc;
    msum += __shfl_xor_sync(FULLMASK, msum, 4);
    msum += __shfl_xor_sync(FULLMASK, msum, 2);
    msum += __shfl_xor_sync(FULLMASK, msum, 1);
    float mmean = msum * 0.125f;
    unsigned lb = (__ballot_sync(FULLMASK, a > 0.1f) >> (grp * 8)) & 0xffu;
    float mload = (float)__popc(lb);

    // ---- stores ------------------------------------------------------------
    if (valid) {
        float* o_m  = out;
        float* o_a  = out + (size_t)B * 512;
        float* o_g  = o_a + (size_t)B * 8;
        float* o_mc = o_g + (size_t)B * 8;
        float* o_ld = o_mc + (size_t)B * 8;
        float* o_ta = o_ld + B;
        float* o_ms = o_ta + B;

        float* om = o_m + (size_t)b * 512 + sub * 8;
        #pragma unroll
        for (int s = 0; s < 8; s++) {
            float4 v0 = make_float4(m[s][0], m[s][1], m[s][2], m[s][3]);
            float4 v1 = make_float4(m[s][4], m[s][5], m[s][6], m[s][7]);
            *(float4*)(om + s * 64)     = v0;
            *(float4*)(om + s * 64 + 4) = v1;
        }
        o_a[sbase]  = a;
        o_g[sbase]  = g;
        o_mc[sbase] = mc;
        if (sub == 0) {
            o_ld[b] = mload;
            o_ta[b] = ta;
            o_ms[b] = mmean;
        }
    }
}

extern "C" void kernel_launch(void* const* d_in, const int* in_sizes, int n_in,
                              void* d_out, int out_size)
{
    const float* mem    = (const float*)d_in[0];
    const float* act_in = (const float*)d_in[1];
    const float* gates  = (const float*)d_in[2];
    const float* thr    = (const float*)d_in[3];
    const float* rstr   = (const float*)d_in[4];
    const float* W      = (const float*)d_in[5];
    const float* maint  = (const float*)d_in[6];
    const float* inp    = (const float*)d_in[7];
    const float* gsig   = (const float*)d_in[8];
    const float* rsig   = (const float*)d_in[9];
    const int*   dtp    = (const int*)d_in[(n_in > 10) ? 10 : (n_in - 1)];
    float* out = (float*)d_out;

    int B = in_sizes[0] / 512;            // [B, 8, 64]
    int batches_per_block = 16;           // 128 threads = 4 warps * 4 batches
    int grid = (B + batches_per_block - 1) / batches_per_block;
    bwm_kernel<<<grid, 128>>>(mem, act_in, gates, thr, rstr, W, maint, inp,
                              gsig, rsig, dtp, out, B);
}

// round 3
// speedup vs baseline: 1.0224x; 1.0224x over previous
#include <cuda_runtime.h>
#include <math.h>
#include <stdint.h>

#define FULLMASK 0xffffffffu

static __device__ __forceinline__ float finf() { return __int_as_float(0x7f800000); }

// ---- packed f32x2 helpers (Blackwell packed FP32; SASS FFMA2 via PTX) ------
static __device__ __forceinline__ unsigned long long pk2(float lo, float hi) {
    unsigned long long u;
    asm("mov.b64 %0, {%1,%2};" : "=l"(u) : "f"(lo), "f"(hi));
    return u;
}
static __device__ __forceinline__ void upk2(unsigned long long u, float& lo, float& hi) {
    asm("mov.b64 {%0,%1}, %2;" : "=f"(lo), "=f"(hi) : "l"(u));
}
static __device__ __forceinline__ unsigned long long fmul2(unsigned long long a, unsigned long long b) {
    unsigned long long r;
    asm("mul.rn.f32x2 %0, %1, %2;" : "=l"(r) : "l"(a), "l"(b));
    return r;
}
static __device__ __forceinline__ unsigned long long ffma2(unsigned long long a, unsigned long long b, unsigned long long c) {
    unsigned long long r;
    asm("fma.rn.f32x2 %0, %1, %2, %3;" : "=l"(r) : "l"(a), "l"(b), "l"(c));
    return r;
}

// One batch per 8-lane group; 4 batches per warp; 128 threads/block.
__global__ void __launch_bounds__(128, 5) bwm_kernel(
    const float* __restrict__ mem,     // [B,8,64]
    const float* __restrict__ act_in,  // [B,8]
    const float* __restrict__ gates,   // [B,8]
    const float* __restrict__ thr,     // [B,8]
    const float* __restrict__ rstr,    // [B,8]
    const float* __restrict__ W,       // [B,8,8]
    const float* __restrict__ maint,   // [B,8]
    const float* __restrict__ inp,     // [B,64]
    const float* __restrict__ gsig,    // [B,8]
    const float* __restrict__ rsig,    // [B,8]
    const int*   __restrict__ dtp,     // scalar
    float* __restrict__ out, int B)
{
    const int gtid = blockIdx.x * blockDim.x + threadIdx.x;
    const int warp = gtid >> 5;
    const int lane = threadIdx.x & 31;
    const int grp  = lane >> 3;     // batch within warp (0..3)
    const int sub  = lane & 7;      // lane within batch group == slot idx for scalars
    const int b0   = warp * 4 + grp;
    const bool valid = (b0 < B);
    const int b = valid ? b0 : (B - 1);

    // dt: int32 or float32 bit pattern
    int dti = *dtp;
    float dt = (dti >= -1000000 && dti <= 1000000) ? (float)dti : __int_as_float(dti);

    // ---- loads: m as packed f32x2 pairs (UNDECAYED; decay folded into epilogue)
    unsigned long long m2[8][4];
    {
        const float* mrow = mem + (size_t)b * 512 + sub * 8;
        #pragma unroll
        for (int s = 0; s < 8; s++) {
            ulonglong2 v0 = *(const ulonglong2*)(mrow + s * 64);
            ulonglong2 v1 = *(const ulonglong2*)(mrow + s * 64 + 4);
            m2[s][0] = v0.x; m2[s][1] = v0.y;
            m2[s][2] = v1.x; m2[s][3] = v1.y;
        }
    }
    float wr[8];
    {
        const float* wp = W + (size_t)b * 64 + sub * 8;   // lane holds W row `sub`
        float4 v0 = *(const float4*)wp;
        float4 v1 = *(const float4*)(wp + 4);
        wr[0] = v0.x; wr[1] = v0.y; wr[2] = v0.z; wr[3] = v0.w;
        wr[4] = v1.x; wr[5] = v1.y; wr[6] = v1.z; wr[7] = v1.w;
    }
    const int sbase = b * 8 + sub;
    float a0  = act_in[sbase];
    float gat = gates[sbase];
    float th  = thr[sbase];
    float rst = rstr[sbase];
    float mnt = maint[sbase];
    float gsg = gsig[sbase];
    float rsg = rsig[sbase];

    // ---- target slot (stable argmin) ---------------------------------------
    bool avail = a0 < 0.2f;
    unsigned avb = (__ballot_sync(FULLMASK, avail) >> (grp * 8)) & 0xffu;
    float key = avb ? (avail ? a0 : finf()) : a0;
    int idx = sub;
    #pragma unroll
    for (int off = 4; off >= 1; off >>= 1) {
        float ok = __shfl_xor_sync(FULLMASK, key, off);
        int   oi = __shfl_xor_sync(FULLMASK, idx, off);
        bool take = (ok < key) || (ok == key && oi < idx);
        key = take ? ok : key;
        idx = take ? oi : idx;
    }
    const int ts = idx;

    // ---- activity decay ----------------------------------------------------
    float a = a0 * 0.9f;
    const unsigned actm = (__ballot_sync(FULLMASK, a > 0.1f) >> (grp * 8)) & 0xffu;

    // ---- squared norms of (undecayed) m; sim is scale-invariant ------------
    float ni[8];
    #pragma unroll
    for (int s = 0; s < 8; s++) {
        unsigned long long acc = fmul2(m2[s][0], m2[s][0]);
        acc = ffma2(m2[s][1], m2[s][1], acc);
        acc = ffma2(m2[s][2], m2[s][2], acc);
        acc = ffma2(m2[s][3], m2[s][3], acc);
        float px, py; upk2(acc, px, py);
        float p = px + py;
        p += __shfl_xor_sync(FULLMASK, p, 4);
        p += __shfl_xor_sync(FULLMASK, p, 2);
        p += __shfl_xor_sync(FULLMASK, p, 1);
        ni[s] = p;
    }

    // ---- interference: 56 serial (i,j) updates on undecayed m --------------
    // c = 0.1*W*sim is invariant under uniform scaling of m, and the update
    // m_i -= c*m_j is scale-equivariant, so the 0.95 decay commutes through
    // this whole loop and is applied once in the epilogue.
    #pragma unroll
    for (int i = 0; i < 8; i++) {
        #pragma unroll
        for (int j = 0; j < 8; j++) {
            if (i == j) continue;
            unsigned long long acc = fmul2(m2[i][0], m2[j][0]);
            acc = ffma2(m2[i][1], m2[j][1], acc);
            acc = ffma2(m2[i][2], m2[j][2], acc);
            acc = ffma2(m2[i][3], m2[j][3], acc);
            float px, py; upk2(acc, px, py);
            float p = px + py;
            p += __shfl_xor_sync(FULLMASK, p, 4);
            p += __shfl_xor_sync(FULLMASK, p, 2);
            p += __shfl_xor_sync(FULLMASK, p, 1);
            float w = __shfl_sync(FULLMASK, wr[j], i, 8);   // W[i][j]
            float sim = p * rsqrtf(fmaxf(ni[i] * ni[j], 1e-24f));
            bool cond = ((actm >> i) & 1u) && ((actm >> j) & 1u);
            float c = cond ? (w * sim * 0.1f) : 0.0f;
            unsigned long long nc2 = pk2(-c, -c);
            m2[i][0] = ffma2(nc2, m2[j][0], m2[i][0]);
            m2[i][1] = ffma2(nc2, m2[j][1], m2[i][1]);
            m2[i][2] = ffma2(nc2, m2[j][2], m2[i][2]);
            m2[i][3] = ffma2(nc2, m2[j][3], m2[i][3]);
            // ||mi - c*mj||^2 = ni - 2 c p + c^2 nj
            ni[i] = fmaf(c, fmaf(c, ni[j], -2.0f * p), ni[i]);
        }
    }

    // ---- inputs ------------------------------------------------------------
    unsigned long long x2[4];
    {
        const float* ip = inp + (size_t)b * 64 + sub * 8;
        ulonglong2 v0 = *(const ulonglong2*)ip;
        ulonglong2 v1 = *(const ulonglong2*)(ip + 4);
        x2[0] = v0.x; x2[1] = v0.y; x2[2] = v1.x; x2[3] = v1.y;
    }

    // ---- gating ------------------------------------------------------------
    float g = fmaf(0.3f, fminf(fmaxf(gsg, 0.0f), 1.0f), 0.7f * gat);
    float gs   = __shfl_sync(FULLMASK, g,  ts, 8);
    float thts = __shfl_sync(FULLMASK, th, ts, 8);
    bool  write = gs > thts;

    // ||inputs||
    float innorm;
    {
        unsigned long long acc = fmul2(x2[0], x2[0]);
        acc = ffma2(x2[1], x2[1], acc);
        acc = ffma2(x2[2], x2[2], acc);
        acc = ffma2(x2[3], x2[3], acc);
        float px, py; upk2(acc, px, py);
        float p = px + py;
        p += __shfl_xor_sync(FULLMASK, p, 4);
        p += __shfl_xor_sync(FULLMASK, p, 2);
        p += __shfl_xor_sync(FULLMASK, p, 1);
        innorm = sqrtf(p);
    }

    // ---- refresh -----------------------------------------------------------
    float ru = fminf(fmaxf(rsg, 0.0f), 1.0f);
    float rs = (ru > 0.1f) ? rst * ru : 0.0f;
    if (write && sub == ts) a = innorm;
    a += rs;

    // ---- maintenance currents ---------------------------------------------
    float mc = (a > 0.1f) ? fmaf(fmaf(0.5f, a, -mnt), 0.1f * dt, mnt) : mnt * 0.95f;

    // ---- capacity deactivation (stable double-argsort rank) ----------------
    bool active = a > 0.1f;
    unsigned ab = (__ballot_sync(FULLMASK, active) >> (grp * 8)) & 0xffu;
    int ndeact = __popc(ab) - 4;   // WM_CAPACITY = 4
    float key2 = active ? a : finf();
    int rank = 0;
    #pragma unroll
    for (int k2 = 0; k2 < 8; k2++) {
        float vk = __shfl_sync(FULLMASK, key2, k2, 8);
        rank += ((vk < key2) || (vk == key2 && k2 < sub)) ? 1 : 0;
    }
    bool deact = active && (rank < ndeact);
    if (deact) a *= 0.5f;
    unsigned db = (__ballot_sync(FULLMASK, deact) >> (grp * 8)) & 0xffu;

    // ---- fused epilogue: decay(0.95) * blend(ts) * (1+rs_s) * 0.7-if-deact -
    float bco = gs * 0.3f;
    #pragma unroll
    for (int s = 0; s < 8; s++) {
        float rss = __shfl_sync(FULLMASK, rs, s, 8);
        float sc = (1.0f + rss) * (((db >> s) & 1u) ? 0.7f : 1.0f);
        float f  = (write && s == ts) ? bco : 0.0f;
        float A  = 0.95f * (1.0f - f) * sc;   // decay folded here
        float Bc = f * sc;
        unsigned long long A2 = pk2(A, A);
        unsigned long long B2 = pk2(Bc, Bc);
        #pragma unroll
        for (int k = 0; k < 4; k++)
            m2[s][k] = ffma2(A2, m2[s][k], fmul2(B2, x2[k]));
    }

    // ---- batch-level reductions -------------------------------------------
    float ta = a;
    ta += __shfl_xor_sync(FULLMASK, ta, 4);
    ta += __shfl_xor_sync(FULLMASK, ta, 2);
    ta += __shfl_xor_sync(FULLMASK, ta, 1);
    float msum = mc;
    msum += __shfl_xor_sync(FULLMASK, msum, 4);
    msum += __shfl_xor_sync(FULLMASK, msum, 2);
    msum += __shfl_xor_sync(FULLMASK, msum, 1);
    float mmean = msum * 0.125f;
    unsigned lb = (__ballot_sync(FULLMASK, a > 0.1f) >> (grp * 8)) & 0xffu;
    float mload = (float)__popc(lb);

    // ---- stores ------------------------------------------------------------
    if (valid) {
        float* o_m  = out;
        float* o_a  = out + (size_t)B * 512;
        float* o_g  = o_a + (size_t)B * 8;
        float* o_mc = o_g + (size_t)B * 8;
        float* o_ld = o_mc + (size_t)B * 8;
        float* o_ta = o_ld + B;
        float* o_ms = o_ta + B;

        float* om = o_m + (size_t)b * 512 + sub * 8;
        #pragma unroll
        for (int s = 0; s < 8; s++) {
            ulonglong2 v0, v1;
            v0.x = m2[s][0]; v0.y = m2[s][1];
            v1.x = m2[s][2]; v1.y = m2[s][3];
            *(ulonglong2*)(om + s * 64)     = v0;
            *(ulonglong2*)(om + s * 64 + 4) = v1;
        }
        o_a[sbase]  = a;
        o_g[sbase]  = g;
        o_mc[sbase] = mc;
        if (sub == 0) {
            o_ld[b] = mload;
            o_ta[b] = ta;
            o_ms[b] = mmean;
        }
    }
}

extern "C" void kernel_launch(void* const* d_in, const int* in_sizes, int n_in,
                              void* d_out, int out_size)
{
    const float* mem    = (const float*)d_in[0];
    const float* act_in = (const float*)d_in[1];
    const float* gates  = (const float*)d_in[2];
    const float* thr    = (const float*)d_in[3];
    const float* rstr   = (const float*)d_in[4];
    const float* W      = (const float*)d_in[5];
    const float* maint  = (const float*)d_in[6];
    const float* inp    = (const float*)d_in[7];
    const float* gsig   = (const float*)d_in[8];
    const float* rsig   = (const float*)d_in[9];
    const int*   dtp    = (const int*)d_in[(n_in > 10) ? 10 : (n_in - 1)];
    float* out = (float*)d_out;

    int B = in_sizes[0] / 512;            // [B, 8, 64]
    int batches_per_block = 16;           // 128 threads = 4 warps * 4 batches
    int grid = (B + batches_per_block - 1) / batches_per_block;
    bwm_kernel<<<grid, 128>>>(mem, act_in, gates, thr, rstr, W, maint, inp,
                              gsig, rsig, dtp, out, B);
}

// round 6
// speedup vs baseline: 1.0972x; 1.0732x over previous
#include <cuda_runtime.h>
#include <math.h>
#include <stdint.h>

#define FULLMASK 0xffffffffu

static __device__ __forceinline__ float finf() { return __int_as_float(0x7f800000); }

// ---- packed f32x2 helpers (SASS FFMA2 via PTX) -----------------------------
static __device__ __forceinline__ unsigned long long pk2(float lo, float hi) {
    unsigned long long u;
    asm("mov.b64 %0, {%1,%2};" : "=l"(u) : "f"(lo), "f"(hi));
    return u;
}
static __device__ __forceinline__ void upk2(unsigned long long u, float& lo, float& hi) {
    asm("mov.b64 {%0,%1}, %2;" : "=f"(lo), "=f"(hi) : "l"(u));
}
static __device__ __forceinline__ unsigned long long fmul2(unsigned long long a, unsigned long long b) {
    unsigned long long r;
    asm("mul.rn.f32x2 %0, %1, %2;" : "=l"(r) : "l"(a), "l"(b));
    return r;
}
static __device__ __forceinline__ unsigned long long ffma2(unsigned long long a, unsigned long long b, unsigned long long c) {
    unsigned long long r;
    asm("fma.rn.f32x2 %0, %1, %2, %3;" : "=l"(r) : "l"(a), "l"(b), "l"(c));
    return r;
}

// Triangle index for symmetric Gram, requires a <= b at every use site.
#define TRI(a,b) ((a)*8 + (b) - ((a)*((a)+1))/2)

// One batch per 8-lane group; 4 batches per warp; 128 threads/block.
__global__ void __launch_bounds__(128) bwm_kernel(
    const float* __restrict__ mem,     // [B,8,64]
    const float* __restrict__ act_in,  // [B,8]
    const float* __restrict__ gates,   // [B,8]
    const float* __restrict__ thr,     // [B,8]
    const float* __restrict__ rstr,    // [B,8]
    const float* __restrict__ W,       // [B,8,8]
    const float* __restrict__ maint,   // [B,8]
    const float* __restrict__ inp,     // [B,64]
    const float* __restrict__ gsig,    // [B,8]
    const float* __restrict__ rsig,    // [B,8]
    const int*   __restrict__ dtp,     // scalar
    float* __restrict__ out, int B)
{
    const int gtid = blockIdx.x * blockDim.x + threadIdx.x;
    const int warp = gtid >> 5;
    const int lane = threadIdx.x & 31;
    const int grp  = lane >> 3;     // batch within warp (0..3)
    const int sub  = lane & 7;      // lane within batch group
    const int b0   = warp * 4 + grp;
    const bool valid = (b0 < B);
    const int b = valid ? b0 : (B - 1);

    int dti = *dtp;
    float dt = (dti >= -1000000 && dti <= 1000000) ? (float)dti : __int_as_float(dti);

    // ---- loads (front-batched, packed) -------------------------------------
    unsigned long long m2[8][4];
    {
        const float* mrow = mem + (size_t)b * 512 + sub * 8;
        #pragma unroll
        for (int s = 0; s < 8; s++) {
            ulonglong2 v0 = *(const ulonglong2*)(mrow + s * 64);
            ulonglong2 v1 = *(const ulonglong2*)(mrow + s * 64 + 4);
            m2[s][0] = v0.x; m2[s][1] = v0.y;
            m2[s][2] = v1.x; m2[s][3] = v1.y;
        }
    }
    float wr[8];
    {
        const float* wp = W + (size_t)b * 64 + sub * 8;   // lane holds W row `sub`
        float4 v0 = *(const float4*)wp;
        float4 v1 = *(const float4*)(wp + 4);
        wr[0] = v0.x; wr[1] = v0.y; wr[2] = v0.z; wr[3] = v0.w;
        wr[4] = v1.x; wr[5] = v1.y; wr[6] = v1.z; wr[7] = v1.w;
    }
    const int sbase = b * 8 + sub;
    float a0  = act_in[sbase];
    float gat = gates[sbase];
    float th  = thr[sbase];
    float rst = rstr[sbase];
    float mnt = maint[sbase];
    float gsg = gsig[sbase];
    float rsg = rsig[sbase];

    // ---- target slot (stable argmin) ---------------------------------------
    bool avail = a0 < 0.2f;
    unsigned avb = (__ballot_sync(FULLMASK, avail) >> (grp * 8)) & 0xffu;
    float key = avb ? (avail ? a0 : finf()) : a0;
    int idx = sub;
    #pragma unroll
    for (int off = 4; off >= 1; off >>= 1) {
        float ok = __shfl_xor_sync(FULLMASK, key, off);
        int   oi = __shfl_xor_sync(FULLMASK, idx, off);
        bool take = (ok < key) || (ok == key && oi < idx);
        key = take ? ok : key;
        idx = take ? oi : idx;
    }
    const int ts = idx;

    // ---- activity decay ----------------------------------------------------
    float a = a0 * 0.9f;
    const unsigned actm = (__ballot_sync(FULLMASK, a > 0.1f) >> (grp * 8)) & 0xffu;

    // ---- Gram matrix of (undecayed) m: 36 unique entries, replicated -------
    // sim is scale-invariant so the 0.95 decay commutes; folded into epilogue.
    float Gt[36];
    #pragma unroll
    for (int aa = 0; aa < 8; aa++) {
        #pragma unroll
        for (int bb = aa; bb < 8; bb++) {
            unsigned long long acc = fmul2(m2[aa][0], m2[bb][0]);
            acc = ffma2(m2[aa][1], m2[bb][1], acc);
            acc = ffma2(m2[aa][2], m2[bb][2], acc);
            acc = ffma2(m2[aa][3], m2[bb][3], acc);
            float px, py; upk2(acc, px, py);
            float p = px + py;
            p += __shfl_xor_sync(FULLMASK, p, 4);
            p += __shfl_xor_sync(FULLMASK, p, 2);
            p += __shfl_xor_sync(FULLMASK, p, 1);
            Gt[TRI(aa,bb)] = p;
        }
    }

    // ---- interference: 56 serial updates, NO shuffles on the chain ---------
    // m_i -= c*m_j transforms the Gram linearly (exact):
    //   G(i,i) -= c*(2*G(i,j) - c*G(j,j))        [uses old G(i,j)]
    //   G(i,k) -= c*G(j,k)   for k != i
    #pragma unroll
    for (int i = 0; i < 8; i++) {
        #pragma unroll
        for (int j = 0; j < 8; j++) {
            if (i == j) continue;
            float p   = (i < j) ? Gt[TRI(i,j)] : Gt[TRI(j,i)];
            float njj = Gt[TRI(j,j)];
            float w = __shfl_sync(FULLMASK, wr[j], i, 8);   // W[i][j]; off-chain
            float sim = p * rsqrtf(fmaxf(Gt[TRI(i,i)] * njj, 1e-24f));
            bool cond = ((actm >> i) & 1u) && ((actm >> j) & 1u);
            float c = cond ? (w * sim * 0.1f) : 0.0f;
            // diagonal first (uses old p)
            Gt[TRI(i,i)] = fmaf(-c, fmaf(-c, njj, 2.0f * p), Gt[TRI(i,i)]);
            // row update, split so triangle indices are single-sided
            #pragma unroll
            for (int k = 0; k < 8; k++) {
                if (k == i) continue;
                float gjk = (j < k) ? Gt[TRI(j,k)] : Gt[TRI(k,j)];
                if (k > i) Gt[TRI(i,k)] = fmaf(-c, gjk, Gt[TRI(i,k)]);
                else       Gt[TRI(k,i)] = fmaf(-c, gjk, Gt[TRI(k,i)]);
            }
            unsigned long long nc2 = pk2(-c, -c);
            m2[i][0] = ffma2(nc2, m2[j][0], m2[i][0]);
            m2[i][1] = ffma2(nc2, m2[j][1], m2[i][1]);
            m2[i][2] = ffma2(nc2, m2[j][2], m2[i][2]);
            m2[i][3] = ffma2(nc2, m2[j][3], m2[i][3]);
        }
    }

    // ---- inputs ------------------------------------------------------------
    unsigned long long x2[4];
    {
        const float* ip = inp + (size_t)b * 64 + sub * 8;
        ulonglong2 v0 = *(const ulonglong2*)ip;
        ulonglong2 v1 = *(const ulonglong2*)(ip + 4);
        x2[0] = v0.x; x2[1] = v0.y; x2[2] = v1.x; x2[3] = v1.y;
    }

    // ---- gating ------------------------------------------------------------
    float g = fmaf(0.3f, fminf(fmaxf(gsg, 0.0f), 1.0f), 0.7f * gat);
    float gs   = __shfl_sync(FULLMASK, g,  ts, 8);
    float thts = __shfl_sync(FULLMASK, th, ts, 8);
    bool  write = gs > thts;

    // ||inputs||
    float innorm;
    {
        unsigned long long acc = fmul2(x2[0], x2[0]);
        acc = ffma2(x2[1], x2[1], acc);
        acc = ffma2(x2[2], x2[2], acc);
        acc = ffma2(x2[3], x2[3], acc);
        float px, py; upk2(acc, px, py);
        float p = px + py;
        p += __shfl_xor_sync(FULLMASK, p, 4);
        p += __shfl_xor_sync(FULLMASK, p, 2);
        p += __shfl_xor_sync(FULLMASK, p, 1);
        innorm = sqrtf(p);
    }

    // ---- refresh -----------------------------------------------------------
    float ru = fminf(fmaxf(rsg, 0.0f), 1.0f);
    float rs = (ru > 0.1f) ? rst * ru : 0.0f;
    if (write && sub == ts) a = innorm;
    a += rs;

    // ---- maintenance currents ---------------------------------------------
    float mc = (a > 0.1f) ? fmaf(fmaf(0.5f, a, -mnt), 0.1f * dt, mnt) : mnt * 0.95f;

    // ---- capacity deactivation (stable double-argsort rank) ----------------
    bool active = a > 0.1f;
    unsigned ab = (__ballot_sync(FULLMASK, active) >> (grp * 8)) & 0xffu;
    int ndeact = __popc(ab) - 4;   // WM_CAPACITY = 4
    float key2 = active ? a : finf();
    int rank = 0;
    #pragma unroll
    for (int k2 = 0; k2 < 8; k2++) {
        float vk = __shfl_sync(FULLMASK, key2, k2, 8);
        rank += ((vk < key2) || (vk == key2 && k2 < sub)) ? 1 : 0;
    }
    bool deact = active && (rank < ndeact);
    if (deact) a *= 0.5f;
    unsigned db = (__ballot_sync(FULLMASK, deact) >> (grp * 8)) & 0xffu;

    // ---- fused epilogue: decay(0.95) * blend(ts) * (1+rs_s) * 0.7-if-deact -
    float bco = gs * 0.3f;
    #pragma unroll
    for (int s = 0; s < 8; s++) {
        float rss = __shfl_sync(FULLMASK, rs, s, 8);
        float sc = (1.0f + rss) * (((db >> s) & 1u) ? 0.7f : 1.0f);
        float f  = (write && s == ts) ? bco : 0.0f;
        float A  = 0.95f * (1.0f - f) * sc;   // decay folded here
        float Bc = f * sc;
        unsigned long long A2 = pk2(A, A);
        unsigned long long B2 = pk2(Bc, Bc);
        #pragma unroll
        for (int k = 0; k < 4; k++)
            m2[s][k] = ffma2(A2, m2[s][k], fmul2(B2, x2[k]));
    }

    // ---- batch-level reductions -------------------------------------------
    float ta = a;
    ta += __shfl_xor_sync(FULLMASK, ta, 4);
    ta += __shfl_xor_sync(FULLMASK, ta, 2);
    ta += __shfl_xor_sync(FULLMASK, ta, 1);
    float msum = mc;
    msum += __shfl_xor_sync(FULLMASK, msum, 4);
    msum += __shfl_xor_sync(FULLMASK, msum, 2);
    msum += __shfl_xor_sync(FULLMASK, msum, 1);
    float mmean = msum * 0.125f;
    unsigned lb = (__ballot_sync(FULLMASK, a > 0.1f) >> (grp * 8)) & 0xffu;
    float mload = (float)__popc(lb);

    // ---- stores ------------------------------------------------------------
    if (valid) {
        float* o_m  = out;
        float* o_a  = out + (size_t)B * 512;
        float* o_g  = o_a + (size_t)B * 8;
        float* o_mc = o_g + (size_t)B * 8;
        float* o_ld = o_mc + (size_t)B * 8;
        float* o_ta = o_ld + B;
        float* o_ms = o_ta + B;

        float* om = o_m + (size_t)b * 512 + sub * 8;
        #pragma unroll
        for (int s = 0; s < 8; s++) {
            ulonglong2 v0, v1;
            v0.x = m2[s][0]; v0.y = m2[s][1];
            v1.x = m2[s][2]; v1.y = m2[s][3];
            *(ulonglong2*)(om + s * 64)     = v0;
            *(ulonglong2*)(om + s * 64 + 4) = v1;
        }
        o_a[sbase]  = a;
        o_g[sbase]  = g;
        o_mc[sbase] = mc;
        if (sub == 0) {
            o_ld[b] = mload;
            o_ta[b] = ta;
            o_ms[b] = mmean;
        }
    }
}

extern "C" void kernel_launch(void* const* d_in, const int* in_sizes, int n_in,
                              void* d_out, int out_size)
{
    const float* mem    = (const float*)d_in[0];
    const float* act_in = (const float*)d_in[1];
    const float* gates  = (const float*)d_in[2];
    const float* thr    = (const float*)d_in[3];
    const float* rstr   = (const float*)d_in[4];
    const float* W      = (const float*)d_in[5];
    const float* maint  = (const float*)d_in[6];
    const float* inp    = (const float*)d_in[7];
    const float* gsig   = (const float*)d_in[8];
    const float* rsig   = (const float*)d_in[9];
    const int*   dtp    = (const int*)d_in[(n_in > 10) ? 10 : (n_in - 1)];
    float* out = (float*)d_out;

    int B = in_sizes[0] / 512;            // [B, 8, 64]
    int batches_per_block = 16;           // 128 threads = 4 warps * 4 batches
    int grid = (B + batches_per_block - 1) / batches_per_block;
    bwm_kernel<<<grid, 128>>>(mem, act_in, gates, thr, rstr, W, maint, inp,
                              gsig, rsig, dtp, out, B);
}

// round 7
// speedup vs baseline: 1.1043x; 1.0065x over previous
#include <cuda_runtime.h>
#include <math.h>
#include <stdint.h>

#define FULLMASK 0xffffffffu

static __device__ __forceinline__ float finf() { return __int_as_float(0x7f800000); }

// ---- packed f32x2 helpers (SASS FFMA2 via PTX) -----------------------------
static __device__ __forceinline__ unsigned long long pk2(float lo, float hi) {
    unsigned long long u;
    asm("mov.b64 %0, {%1,%2};" : "=l"(u) : "f"(lo), "f"(hi));
    return u;
}
static __device__ __forceinline__ void upk2(unsigned long long u, float& lo, float& hi) {
    asm("mov.b64 {%0,%1}, %2;" : "=f"(lo), "=f"(hi) : "l"(u));
}
static __device__ __forceinline__ unsigned long long fmul2(unsigned long long a, unsigned long long b) {
    unsigned long long r;
    asm("mul.rn.f32x2 %0, %1, %2;" : "=l"(r) : "l"(a), "l"(b));
    return r;
}
static __device__ __forceinline__ unsigned long long ffma2(unsigned long long a, unsigned long long b, unsigned long long c) {
    unsigned long long r;
    asm("fma.rn.f32x2 %0, %1, %2, %3;" : "=l"(r) : "l"(a), "l"(b), "l"(c));
    return r;
}

// scalar dot partial of two 4xpk2 chunks -> one float (lane-local part)
static __device__ __forceinline__ float dot4(const unsigned long long* u,
                                             const unsigned long long* v) {
    unsigned long long acc = fmul2(u[0], v[0]);
    acc = ffma2(u[1], v[1], acc);
    acc = ffma2(u[2], v[2], acc);
    acc = ffma2(u[3], v[3], acc);
    float x, y; upk2(acc, x, y);
    return x + y;
}
static __device__ __forceinline__ float red8(float p) {
    p += __shfl_xor_sync(FULLMASK, p, 4);
    p += __shfl_xor_sync(FULLMASK, p, 2);
    p += __shfl_xor_sync(FULLMASK, p, 1);
    return p;
}

// Triangle index for symmetric Gram, requires a <= b at use site.
#define TRI(a,b) ((a)*8 + (b) - ((a)*((a)+1))/2)

// Per-thread smem stash: 64 floats + 4 pad (272B stride => conflict-free phases)
#define STASH_STRIDE 68

// One batch per 8-lane group; 4 batches per warp; 128 threads/block.
__global__ void __launch_bounds__(128, 4) bwm_kernel(
    const float* __restrict__ mem,     // [B,8,64]
    const float* __restrict__ act_in,  // [B,8]
    const float* __restrict__ gates,   // [B,8]
    const float* __restrict__ thr,     // [B,8]
    const float* __restrict__ rstr,    // [B,8]
    const float* __restrict__ W,       // [B,8,8]
    const float* __restrict__ maint,   // [B,8]
    const float* __restrict__ inp,     // [B,64]
    const float* __restrict__ gsig,    // [B,8]
    const float* __restrict__ rsig,    // [B,8]
    const int*   __restrict__ dtp,     // scalar
    float* __restrict__ out, int B)
{
    __shared__ float stash[128 * STASH_STRIDE];   // 34816 B, thread-private use

    const int tid  = threadIdx.x;
    const int gtid = blockIdx.x * blockDim.x + tid;
    const int warp = gtid >> 5;
    const int lane = tid & 31;
    const int grp  = lane >> 3;
    const int sub  = lane & 7;
    const int b0   = warp * 4 + grp;
    const bool valid = (b0 < B);
    const int b = valid ? b0 : (B - 1);

    float* myst = stash + tid * STASH_STRIDE;     // my 64-float stash

    int dti = *dtp;
    float dt = (dti >= -1000000 && dti <= 1000000) ? (float)dti : __int_as_float(dti);

    const float* mrow = mem + (size_t)b * 512 + sub * 8;

    // scalar loads (early, front-batched with vector loads)
    const int sbase = b * 8 + sub;
    float a0  = act_in[sbase];
    float gat = gates[sbase];
    float th  = thr[sbase];
    float rst = rstr[sbase];
    float mnt = maint[sbase];
    float gsg = gsig[sbase];
    float rsg = rsig[sbase];
    float wr[8];
    {
        const float* wp = W + (size_t)b * 64 + sub * 8;
        float4 v0 = *(const float4*)wp;
        float4 v1 = *(const float4*)(wp + 4);
        wr[0] = v0.x; wr[1] = v0.y; wr[2] = v0.z; wr[3] = v0.w;
        wr[4] = v1.x; wr[5] = v1.y; wr[6] = v1.z; wr[7] = v1.w;
    }
    unsigned long long x2[4];
    {
        const float* ip = inp + (size_t)b * 64 + sub * 8;
        ulonglong2 v0 = *(const ulonglong2*)ip;
        ulonglong2 v1 = *(const ulonglong2*)(ip + 4);
        x2[0] = v0.x; x2[1] = v0.y; x2[2] = v1.x; x2[3] = v1.y;
    }

    // ---- Gram build in two halves (keeps only 4 slots in regs at a time) ---
    float Pt[36];   // lane-local dot partials, reduced in bulk afterwards
    {
        unsigned long long mh[4][4];
        // half A: slots 0..3
        #pragma unroll
        for (int s = 0; s < 4; s++) {
            ulonglong2 v0 = *(const ulonglong2*)(mrow + s * 64);
            ulonglong2 v1 = *(const ulonglong2*)(mrow + s * 64 + 4);
            mh[s][0] = v0.x; mh[s][1] = v0.y; mh[s][2] = v1.x; mh[s][3] = v1.y;
        }
        #pragma unroll
        for (int aa = 0; aa < 4; aa++)
            #pragma unroll
            for (int bb = aa; bb < 4; bb++)
                Pt[TRI(aa,bb)] = dot4(mh[aa], mh[bb]);
        #pragma unroll
        for (int s = 0; s < 4; s++) {
            *(ulonglong2*)(myst + s * 8)     = make_ulonglong2(mh[s][0], mh[s][1]);
            *(ulonglong2*)(myst + s * 8 + 4) = make_ulonglong2(mh[s][2], mh[s][3]);
        }
        // half B: slots 4..7
        #pragma unroll
        for (int s = 0; s < 4; s++) {
            ulonglong2 v0 = *(const ulonglong2*)(mrow + (s + 4) * 64);
            ulonglong2 v1 = *(const ulonglong2*)(mrow + (s + 4) * 64 + 4);
            mh[s][0] = v0.x; mh[s][1] = v0.y; mh[s][2] = v1.x; mh[s][3] = v1.y;
        }
        #pragma unroll
        for (int aa = 0; aa < 4; aa++)
            #pragma unroll
            for (int bb = aa; bb < 4; bb++)
                Pt[TRI(aa+4,bb+4)] = dot4(mh[aa], mh[bb]);
        // cross: reload half-A chunks from own stash (no barrier: same thread)
        #pragma unroll
        for (int aa = 0; aa < 4; aa++) {
            unsigned long long ca[4];
            ulonglong2 v0 = *(const ulonglong2*)(myst + aa * 8);
            ulonglong2 v1 = *(const ulonglong2*)(myst + aa * 8 + 4);
            ca[0] = v0.x; ca[1] = v0.y; ca[2] = v1.x; ca[3] = v1.y;
            #pragma unroll
            for (int bb = 0; bb < 4; bb++)
                Pt[TRI(aa,bb+4)] = dot4(ca, mh[bb]);
        }
        #pragma unroll
        for (int s = 0; s < 4; s++) {
            *(ulonglong2*)(myst + (s + 4) * 8)     = make_ulonglong2(mh[s][0], mh[s][1]);
            *(ulonglong2*)(myst + (s + 4) * 8 + 4) = make_ulonglong2(mh[s][2], mh[s][3]);
        }
    }
    // bulk butterfly reduction (independent -> pipelined)
    float Gt[36];
    #pragma unroll
    for (int e = 0; e < 36; e++) Gt[e] = red8(Pt[e]);

    // ---- target slot (stable argmin) ---------------------------------------
    bool avail = a0 < 0.2f;
    unsigned avb = (__ballot_sync(FULLMASK, avail) >> (grp * 8)) & 0xffu;
    float key = avb ? (avail ? a0 : finf()) : a0;
    int idx = sub;
    #pragma unroll
    for (int off = 4; off >= 1; off >>= 1) {
        float ok = __shfl_xor_sync(FULLMASK, key, off);
        int   oi = __shfl_xor_sync(FULLMASK, idx, off);
        bool take = (ok < key) || (ok == key && oi < idx);
        key = take ? ok : key;
        idx = take ? oi : idx;
    }
    const int ts = idx;

    float a = a0 * 0.9f;
    const unsigned actm = (__ballot_sync(FULLMASK, a > 0.1f) >> (grp * 8)) & 0xffu;

    // ---- scalar interference loop: Gram recurrence + transform T -----------
    // T starts as I; step (i,j): row_i(T) -= c * row_j(T).
    // Lane `sub` holds column `sub` of T: Tcol[i] = T[i][sub].
    float Tcol[8];
    #pragma unroll
    for (int i = 0; i < 8; i++) Tcol[i] = (i == sub) ? 1.0f : 0.0f;

    #pragma unroll
    for (int i = 0; i < 8; i++) {
        #pragma unroll
        for (int j = 0; j < 8; j++) {
            if (i == j) continue;
            float p   = (i < j) ? Gt[TRI(i,j)] : Gt[TRI(j,i)];
            float njj = Gt[TRI(j,j)];
            float w = __shfl_sync(FULLMASK, wr[j], i, 8);   // W[i][j]
            float sim = p * rsqrtf(fmaxf(Gt[TRI(i,i)] * njj, 1e-24f));
            bool cond = ((actm >> i) & 1u) && ((actm >> j) & 1u);
            float c = cond ? (w * sim * 0.1f) : 0.0f;
            Gt[TRI(i,i)] = fmaf(-c, fmaf(-c, njj, 2.0f * p), Gt[TRI(i,i)]);
            #pragma unroll
            for (int k = 0; k < 8; k++) {
                if (k == i) continue;
                float gjk = (j < k) ? Gt[TRI(j,k)] : Gt[TRI(k,j)];
                if (k > i) Gt[TRI(i,k)] = fmaf(-c, gjk, Gt[TRI(i,k)]);
                else       Gt[TRI(k,i)] = fmaf(-c, gjk, Gt[TRI(k,i)]);
            }
            Tcol[i] = fmaf(-c, Tcol[j], Tcol[i]);
        }
    }

    // ---- gating / refresh / maintenance / deactivation ---------------------
    float g = fmaf(0.3f, fminf(fmaxf(gsg, 0.0f), 1.0f), 0.7f * gat);
    float gs   = __shfl_sync(FULLMASK, g,  ts, 8);
    float thts = __shfl_sync(FULLMASK, th, ts, 8);
    bool  write = gs > thts;

    float innorm = sqrtf(red8(dot4(x2, x2)));

    float ru = fminf(fmaxf(rsg, 0.0f), 1.0f);
    float rs = (ru > 0.1f) ? rst * ru : 0.0f;
    if (write && sub == ts) a = innorm;
    a += rs;

    float mc = (a > 0.1f) ? fmaf(fmaf(0.5f, a, -mnt), 0.1f * dt, mnt) : mnt * 0.95f;

    bool active = a > 0.1f;
    unsigned ab = (__ballot_sync(FULLMASK, active) >> (grp * 8)) & 0xffu;
    int ndeact = __popc(ab) - 4;   // WM_CAPACITY = 4
    float key2 = active ? a : finf();
    int rank = 0;
    #pragma unroll
    for (int k2 = 0; k2 < 8; k2++) {
        float vk = __shfl_sync(FULLMASK, key2, k2, 8);
        rank += ((vk < key2) || (vk == key2 && k2 < sub)) ? 1 : 0;
    }
    bool deact = active && (rank < ndeact);
    if (deact) a *= 0.5f;

    // ---- fold epilogue row-scale into T ------------------------------------
    // For own slot `sub`: sc, blend fraction f, A (with 0.95 decay), B.
    float bco = gs * 0.3f;
    float sc  = (1.0f + rs) * (deact ? 0.7f : 1.0f);
    float f   = (write && sub == ts) ? bco : 0.0f;
    float A_own = 0.95f * (1.0f - f) * sc;
    float B_own = f * sc;
    #pragma unroll
    for (int i = 0; i < 8; i++)
        Tcol[i] *= __shfl_sync(FULLMASK, A_own, i, 8);   // T' = diag(A)*T
    float Bts = __shfl_sync(FULLMASK, B_own, ts, 8);      // 0 if !write

    // ---- apply m_fin = T' * m0 + e_ts * (Bts * x), j-outer ----------------
    unsigned long long acc[8][4];
    #pragma unroll
    for (int i = 0; i < 8; i++) {
        float Bi = (i == ts) ? Bts : 0.0f;
        unsigned long long B2 = pk2(Bi, Bi);
        #pragma unroll
        for (int k = 0; k < 4; k++) acc[i][k] = fmul2(B2, x2[k]);
    }
    #pragma unroll
    for (int j = 0; j < 8; j++) {
        unsigned long long mj[4];
        ulonglong2 v0 = *(const ulonglong2*)(myst + j * 8);
        ulonglong2 v1 = *(const ulonglong2*)(myst + j * 8 + 4);
        mj[0] = v0.x; mj[1] = v0.y; mj[2] = v1.x; mj[3] = v1.y;
        #pragma unroll
        for (int i = 0; i < 8; i++) {
            float t = __shfl_sync(FULLMASK, Tcol[i], j, 8);   // T'[i][j]
            unsigned long long t2 = pk2(t, t);
            #pragma unroll
            for (int k = 0; k < 4; k++)
                acc[i][k] = ffma2(t2, mj[k], acc[i][k]);
        }
    }

    // ---- batch-level reductions -------------------------------------------
    float ta = red8(a);
    float mmean = red8(mc) * 0.125f;
    unsigned lb = (__ballot_sync(FULLMASK, a > 0.1f) >> (grp * 8)) & 0xffu;
    float mload = (float)__popc(lb);

    // ---- stores ------------------------------------------------------------
    if (valid) {
        float* o_m  = out;
        float* o_a  = out + (size_t)B * 512;
        float* o_g  = o_a + (size_t)B * 8;
        float* o_mc = o_g + (size_t)B * 8;
        float* o_ld = o_mc + (size_t)B * 8;
        float* o_ta = o_ld + B;
        float* o_ms = o_ta + B;

        float* om = o_m + (size_t)b * 512 + sub * 8;
        #pragma unroll
        for (int s = 0; s < 8; s++) {
            *(ulonglong2*)(om + s * 64)     = make_ulonglong2(acc[s][0], acc[s][1]);
            *(ulonglong2*)(om + s * 64 + 4) = make_ulonglong2(acc[s][2], acc[s][3]);
        }
        o_a[sbase]  = a;
        o_g[sbase]  = g;
        o_mc[sbase] = mc;
        if (sub == 0) {
            o_ld[b] = mload;
            o_ta[b] = ta;
            o_ms[b] = mmean;
        }
    }
}

extern "C" void kernel_launch(void* const* d_in, const int* in_sizes, int n_in,
                              void* d_out, int out_size)
{
    const float* mem    = (const float*)d_in[0];
    const float* act_in = (const float*)d_in[1];
    const float* gates  = (const float*)d_in[2];
    const float* thr    = (const float*)d_in[3];
    const float* rstr   = (const float*)d_in[4];
    const float* W      = (const float*)d_in[5];
    const float* maint  = (const float*)d_in[6];
    const float* inp    = (const float*)d_in[7];
    const float* gsig   = (const float*)d_in[8];
    const float* rsig   = (const float*)d_in[9];
    const int*   dtp    = (const int*)d_in[(n_in > 10) ? 10 : (n_in - 1)];
    float* out = (float*)d_out;

    int B = in_sizes[0] / 512;            // [B, 8, 64]
    int batches_per_block = 16;           // 128 threads = 4 warps * 4 batches
    int grid = (B + batches_per_block - 1) / batches_per_block;
    bwm_kernel<<<grid, 128>>>(mem, act_in, gates, thr, rstr, W, maint, inp,
                              gsig, rsig, dtp, out, B);
}